// round 1
// baseline (speedup 1.0000x reference)
#include <cuda_runtime.h>
#include <cuda_bf16.h>
#include <math.h>

// Problem constants
#define B_  4
#define S_  2048
#define D_  1024
#define BS_ (B_ * S_)          // 8192

// ---------------- scratch (static device globals; no runtime allocation) ----
__device__ float g_Q[BS_ * D_];        // 32 MB
__device__ float g_Kh[BS_ * D_];       // 32 MB
__device__ float g_V[BS_ * D_];        // 32 MB
__device__ float g_S[B_ * S_ * S_];    // 64 MB  (scores / probs in place)
__device__ float g_Wkr[D_ * D_];       // 4 MB
__device__ float g_bkr[D_];

// ---------------------------------------------------------------------------
// bkr[r] = br[r] + sum_d bk[d] * Wr[d, r]
__global__ void bkr_kernel(const float* __restrict__ bk,
                           const float* __restrict__ Wr,
                           const float* __restrict__ br,
                           float* __restrict__ bkr, int D)
{
    int r = blockIdx.x * blockDim.x + threadIdx.x;
    if (r >= D) return;
    float s = br[r];
    for (int d = 0; d < D; ++d)
        s += bk[d] * Wr[(long)d * D + r];
    bkr[r] = s;
}

// ---------------------------------------------------------------------------
// Generic fp32 SGEMM, 128x128 block tile, BK=8, 256 threads, 8x8 per thread.
// C = op( A @ B(^T) + bias ),  op = identity or cosf.
// Batched via blockIdx.z with element strides sA, sB, sC.
// All dims assumed divisible by 128 (M, N) and 8 (K) — true for every call here.
template<int EPI_COS, int TRANS_B>
__global__ __launch_bounds__(256, 2)
void sgemm_k(const float* __restrict__ A, const float* __restrict__ B,
             const float* __restrict__ bias, float* __restrict__ C,
             int M, int N, int K, long sA, long sB, long sC)
{
    const int BM = 128, BN = 128, BK = 8;
    __shared__ float As[BK][BM];
    __shared__ float Bs[BK][BN];

    A += (long)blockIdx.z * sA;
    B += (long)blockIdx.z * sB;
    C += (long)blockIdx.z * sC;

    const int m0 = blockIdx.y * BM;
    const int n0 = blockIdx.x * BN;
    const int t  = threadIdx.x;
    const int tx = t & 15;        // 0..15  (n direction)
    const int ty = t >> 4;        // 0..15  (m direction)

    // A-load mapping: 128 rows x 8 cols, one float4 per thread
    const int ar = t >> 1;
    const int ac = (t & 1) * 4;
    // B-load mapping
    const int bnr = t >> 1;            // trans: N-row
    const int bkc = (t & 1) * 4;       // trans: k offset
    const int bkr_ = t >> 5;           // non-trans: k-row 0..7
    const int bnc = (t & 31) * 4;      // non-trans: n offset

    float acc[8][8];
#pragma unroll
    for (int i = 0; i < 8; ++i)
#pragma unroll
        for (int j = 0; j < 8; ++j) acc[i][j] = 0.f;

    for (int k0 = 0; k0 < K; k0 += BK) {
        // load A tile (transposed into smem)
        float4 av = *(const float4*)(A + (long)(m0 + ar) * K + k0 + ac);
        As[ac + 0][ar] = av.x;
        As[ac + 1][ar] = av.y;
        As[ac + 2][ar] = av.z;
        As[ac + 3][ar] = av.w;

        if (TRANS_B) {
            // B is N x K row-major; need Bs[kk][nn] = B[n0+nn, k0+kk]
            float4 bv = *(const float4*)(B + (long)(n0 + bnr) * K + k0 + bkc);
            Bs[bkc + 0][bnr] = bv.x;
            Bs[bkc + 1][bnr] = bv.y;
            Bs[bkc + 2][bnr] = bv.z;
            Bs[bkc + 3][bnr] = bv.w;
        } else {
            // B is K x N row-major
            float4 bv = *(const float4*)(B + (long)(k0 + bkr_) * N + n0 + bnc);
            *(float4*)&Bs[bkr_][bnc] = bv;
        }
        __syncthreads();

#pragma unroll
        for (int kk = 0; kk < BK; ++kk) {
            float af[8], bf[8];
#pragma unroll
            for (int i = 0; i < 8; ++i) af[i] = As[kk][ty * 8 + i];
#pragma unroll
            for (int j = 0; j < 8; ++j) bf[j] = Bs[kk][tx * 8 + j];
#pragma unroll
            for (int i = 0; i < 8; ++i)
#pragma unroll
                for (int j = 0; j < 8; ++j)
                    acc[i][j] += af[i] * bf[j];
        }
        __syncthreads();
    }

    // epilogue
    float bv[8];
#pragma unroll
    for (int j = 0; j < 8; ++j)
        bv[j] = bias ? bias[n0 + tx * 8 + j] : 0.f;

#pragma unroll
    for (int i = 0; i < 8; ++i) {
        float out[8];
#pragma unroll
        for (int j = 0; j < 8; ++j) {
            float v = acc[i][j] + bv[j];
            if (EPI_COS) v = cosf(v);
            out[j] = v;
        }
        float* cp = C + (long)(m0 + ty * 8 + i) * N + n0 + tx * 8;
        *(float4*)(cp + 0) = make_float4(out[0], out[1], out[2], out[3]);
        *(float4*)(cp + 4) = make_float4(out[4], out[5], out[6], out[7]);
    }
}

// ---------------------------------------------------------------------------
// Row softmax over ncols=2048, one block (256 threads) per row, values in regs.
__global__ void softmax_rows(float* __restrict__ scores)
{
    const int NCOL = S_;
    float* p = scores + (long)blockIdx.x * NCOL;
    const int t = threadIdx.x;

    __shared__ float red[32];

    float v[NCOL / 256];
#pragma unroll
    for (int i = 0; i < NCOL / 256; ++i) v[i] = p[t + i * 256];

    // max reduce
    float mx = v[0];
#pragma unroll
    for (int i = 1; i < NCOL / 256; ++i) mx = fmaxf(mx, v[i]);
#pragma unroll
    for (int o = 16; o > 0; o >>= 1) mx = fmaxf(mx, __shfl_xor_sync(0xffffffffu, mx, o));
    if ((t & 31) == 0) red[t >> 5] = mx;
    __syncthreads();
    mx = red[t & 7];
#pragma unroll
    for (int o = 4; o > 0; o >>= 1) mx = fmaxf(mx, __shfl_xor_sync(0xffffffffu, mx, o));
    // broadcast full max via one more shared round
    __syncthreads();
    if (t == 0) {
        float m = red[0];
        for (int i = 1; i < 8; ++i) m = fmaxf(m, red[i]);
        red[0] = m;
    }
    __syncthreads();
    mx = red[0];

    // exp + sum
    float s = 0.f;
#pragma unroll
    for (int i = 0; i < NCOL / 256; ++i) { v[i] = expf(v[i] - mx); s += v[i]; }
#pragma unroll
    for (int o = 16; o > 0; o >>= 1) s += __shfl_xor_sync(0xffffffffu, s, o);
    __syncthreads();
    if ((t & 31) == 0) red[t >> 5] = s;
    __syncthreads();
    if (t == 0) {
        float ss = 0.f;
        for (int i = 0; i < 8; ++i) ss += red[i];
        red[0] = 1.f / ss;
    }
    __syncthreads();
    const float inv = red[0];

#pragma unroll
    for (int i = 0; i < NCOL / 256; ++i) p[t + i * 256] = v[i] * inv;
}

// ---------------------------------------------------------------------------
extern "C" void kernel_launch(void* const* d_in, const int* in_sizes, int n_in,
                              void* d_out, int out_size)
{
    const float* x  = (const float*)d_in[0];
    const float* y  = (const float*)d_in[1];
    const float* Wq = (const float*)d_in[2];
    const float* bq = (const float*)d_in[3];
    const float* Wk = (const float*)d_in[4];
    const float* bk = (const float*)d_in[5];
    const float* Wv = (const float*)d_in[6];
    const float* bv = (const float*)d_in[7];
    const float* Wr = (const float*)d_in[8];
    const float* br = (const float*)d_in[9];
    float* out = (float*)d_out;

    float *Q, *Kh, *V, *Sc, *Wkr, *bkr;
    cudaGetSymbolAddress((void**)&Q,   g_Q);
    cudaGetSymbolAddress((void**)&Kh,  g_Kh);
    cudaGetSymbolAddress((void**)&V,   g_V);
    cudaGetSymbolAddress((void**)&Sc,  g_S);
    cudaGetSymbolAddress((void**)&Wkr, g_Wkr);
    cudaGetSymbolAddress((void**)&bkr, g_bkr);

    // 1) bkr = bk @ Wr + br
    bkr_kernel<<<D_ / 256, 256>>>(bk, Wr, br, bkr, D_);

    // 2) Wkr = Wk @ Wr  (1024x1024x1024)
    {
        dim3 g(D_ / 128, D_ / 128, 1);
        sgemm_k<0, 0><<<g, 256>>>(Wk, Wr, nullptr, Wkr, D_, D_, D_, 0, 0, 0);
    }

    // 3) Q = x @ Wq + bq   (8192 x 1024 x 1024)
    {
        dim3 g(D_ / 128, BS_ / 128, 1);
        sgemm_k<0, 0><<<g, 256>>>(x, Wq, bq, Q, BS_, D_, D_, 0, 0, 0);
    }

    // 4) Kh = cos(y @ Wkr + bkr)
    {
        dim3 g(D_ / 128, BS_ / 128, 1);
        sgemm_k<1, 0><<<g, 256>>>(y, Wkr, bkr, Kh, BS_, D_, D_, 0, 0, 0);
    }

    // 5) V = y @ Wv + bv
    {
        dim3 g(D_ / 128, BS_ / 128, 1);
        sgemm_k<0, 0><<<g, 256>>>(y, Wv, bv, V, BS_, D_, D_, 0, 0, 0);
    }

    // 6) scores[b] = Q[b] @ Kh[b]^T   (2048 x 2048 x 1024, batched)
    {
        dim3 g(S_ / 128, S_ / 128, B_);
        sgemm_k<0, 1><<<g, 256>>>(Q, Kh, nullptr, Sc, S_, S_, D_,
                                  (long)S_ * D_, (long)S_ * D_, (long)S_ * S_);
    }

    // 7) softmax rows (in place)
    softmax_rows<<<B_ * S_, 256>>>(Sc);

    // 8) out[b] = probs[b] @ V[b]   (2048 x 1024 x 2048, batched)
    {
        dim3 g(D_ / 128, S_ / 128, B_);
        sgemm_k<0, 0><<<g, 256>>>(Sc, V, nullptr, out, S_, D_, S_,
                                  (long)S_ * S_, (long)S_ * D_, (long)S_ * D_);
    }
}

// round 2
// speedup vs baseline: 1.3804x; 1.3804x over previous
#include <cuda_runtime.h>
#include <cuda_bf16.h>
#include <cstdint>
#include <math.h>

// Problem constants
#define B_  4
#define S_  2048
#define D_  1024
#define BS_ (B_ * S_)          // 8192

// ---------------- scratch (static device globals; no runtime allocation) ----
__device__ float g_Q[BS_ * D_];        // 32 MB
__device__ float g_Kh[BS_ * D_];       // 32 MB
__device__ float g_V[BS_ * D_];        // 32 MB
__device__ float g_S[B_ * S_ * S_];    // 64 MB  (scores / probs in place)
__device__ float g_Wkr[D_ * D_];       // 4 MB
__device__ float g_bkr[D_];

// ---------------------------------------------------------------------------
__device__ __forceinline__ uint32_t f2tf32(float x) {
    uint32_t r;
    asm("cvt.rna.tf32.f32 %0, %1;" : "=r"(r) : "f"(x));
    return r;
}

__device__ __forceinline__ void mma8(float* d, const uint32_t* a, const uint32_t* b) {
    asm volatile(
        "mma.sync.aligned.m16n8k8.row.col.f32.tf32.tf32.f32 "
        "{%0,%1,%2,%3}, {%4,%5,%6,%7}, {%8,%9}, {%0,%1,%2,%3};"
        : "+f"(d[0]), "+f"(d[1]), "+f"(d[2]), "+f"(d[3])
        : "r"(a[0]), "r"(a[1]), "r"(a[2]), "r"(a[3]),
          "r"(b[0]), "r"(b[1]));
}

// ---------------------------------------------------------------------------
// Tensor-core fp32 GEMM via 3xTF32 decomposition.
// C = op( A @ B(^T) + bias ), op = identity or cosf.
// Block tile 128x128, BK=16, 8 warps (2 M x 4 N), warp tile 64x32.
// M, N divisible by 128; K divisible by 16 (true for every call here).
template<int EPI_COS, int TRANS_B>
__global__ __launch_bounds__(256, 1)
void mma_gemm(const float* __restrict__ A, const float* __restrict__ Bm,
              const float* __restrict__ bias, float* __restrict__ C,
              int M, int N, int K, long sA, long sB, long sC)
{
    const int BM = 128, BN = 128, BK = 16, PAD = 8;
    __shared__ float As[2][BK][BM + PAD];
    __shared__ float Bs[2][BK][BN + PAD];

    A  += (long)blockIdx.z * sA;
    Bm += (long)blockIdx.z * sB;
    C  += (long)blockIdx.z * sC;

    const int m0 = blockIdx.y * BM;
    const int n0 = blockIdx.x * BN;
    const int t    = threadIdx.x;
    const int lane = t & 31;
    const int w    = t >> 5;
    const int g    = lane >> 2;   // groupID 0..7
    const int tg   = lane & 3;    // threadID_in_group 0..3
    const int wm   = w & 1;       // 2 warps in M
    const int wn   = w >> 1;      // 4 warps in N

    // global->smem load mappings
    const int a_r  = t >> 2;          // 0..63 (A row within tile; +64 for 2nd)
    const int a_c  = (t & 3) * 4;     // k offset
    const int bt_r = t >> 2;          // trans: N-row within tile
    const int bt_c = (t & 3) * 4;     // trans: k offset
    const int bn_r = t >> 4;          // non-trans: k-row 0..15
    const int bn_c = (t & 15) * 8;    // non-trans: n offset (2 float4)

    float4 pa0, pa1, pb0, pb1;

    auto gload = [&](int kt) {
        const float* Ap = A + (long)(m0 + a_r) * K + kt * BK + a_c;
        pa0 = *(const float4*)Ap;
        pa1 = *(const float4*)(Ap + 64L * K);
        if (TRANS_B) {
            const float* Bp = Bm + (long)(n0 + bt_r) * K + kt * BK + bt_c;
            pb0 = *(const float4*)Bp;
            pb1 = *(const float4*)(Bp + 64L * K);
        } else {
            const float* Bp = Bm + (long)(kt * BK + bn_r) * N + n0 + bn_c;
            pb0 = *(const float4*)Bp;
            pb1 = *(const float4*)(Bp + 4);
        }
    };

    auto sstore = [&](int buf) {
        As[buf][a_c + 0][a_r] = pa0.x;
        As[buf][a_c + 1][a_r] = pa0.y;
        As[buf][a_c + 2][a_r] = pa0.z;
        As[buf][a_c + 3][a_r] = pa0.w;
        As[buf][a_c + 0][a_r + 64] = pa1.x;
        As[buf][a_c + 1][a_r + 64] = pa1.y;
        As[buf][a_c + 2][a_r + 64] = pa1.z;
        As[buf][a_c + 3][a_r + 64] = pa1.w;
        if (TRANS_B) {
            Bs[buf][bt_c + 0][bt_r] = pb0.x;
            Bs[buf][bt_c + 1][bt_r] = pb0.y;
            Bs[buf][bt_c + 2][bt_r] = pb0.z;
            Bs[buf][bt_c + 3][bt_r] = pb0.w;
            Bs[buf][bt_c + 0][bt_r + 64] = pb1.x;
            Bs[buf][bt_c + 1][bt_r + 64] = pb1.y;
            Bs[buf][bt_c + 2][bt_r + 64] = pb1.z;
            Bs[buf][bt_c + 3][bt_r + 64] = pb1.w;
        } else {
            *(float4*)&Bs[buf][bn_r][bn_c]     = pb0;
            *(float4*)&Bs[buf][bn_r][bn_c + 4] = pb1;
        }
    };

    float acc[4][4][4];
#pragma unroll
    for (int i = 0; i < 4; ++i)
#pragma unroll
        for (int j = 0; j < 4; ++j)
#pragma unroll
            for (int r = 0; r < 4; ++r) acc[i][j][r] = 0.f;

    const int KT = K / BK;
    gload(0);
    sstore(0);
    __syncthreads();

    for (int kt = 0; kt < KT; ++kt) {
        const int cur = kt & 1;
        if (kt + 1 < KT) gload(kt + 1);

#pragma unroll
        for (int ks = 0; ks < BK; ks += 8) {
            uint32_t ahi[4][4], alo[4][4], bhi[4][2], blo[4][2];
#pragma unroll
            for (int mt = 0; mt < 4; ++mt) {
                const int mb = wm * 64 + mt * 16;
                // a0:(g,tg) a1:(g+8,tg) a2:(g,tg+4) a3:(g+8,tg+4)
                float f0 = As[cur][ks + tg][mb + g];
                float f1 = As[cur][ks + tg][mb + g + 8];
                float f2 = As[cur][ks + tg + 4][mb + g];
                float f3 = As[cur][ks + tg + 4][mb + g + 8];
                ahi[mt][0] = f2tf32(f0); alo[mt][0] = f2tf32(f0 - __uint_as_float(ahi[mt][0]));
                ahi[mt][1] = f2tf32(f1); alo[mt][1] = f2tf32(f1 - __uint_as_float(ahi[mt][1]));
                ahi[mt][2] = f2tf32(f2); alo[mt][2] = f2tf32(f2 - __uint_as_float(ahi[mt][2]));
                ahi[mt][3] = f2tf32(f3); alo[mt][3] = f2tf32(f3 - __uint_as_float(ahi[mt][3]));
            }
#pragma unroll
            for (int nt = 0; nt < 4; ++nt) {
                const int nb = wn * 32 + nt * 8;
                // b0:(k=tg,n=g) b1:(k=tg+4,n=g)
                float h0 = Bs[cur][ks + tg][nb + g];
                float h1 = Bs[cur][ks + tg + 4][nb + g];
                bhi[nt][0] = f2tf32(h0); blo[nt][0] = f2tf32(h0 - __uint_as_float(bhi[nt][0]));
                bhi[nt][1] = f2tf32(h1); blo[nt][1] = f2tf32(h1 - __uint_as_float(bhi[nt][1]));
            }
#pragma unroll
            for (int mt = 0; mt < 4; ++mt)
#pragma unroll
                for (int nt = 0; nt < 4; ++nt) {
                    mma8(acc[mt][nt], ahi[mt], bhi[nt]);
                    mma8(acc[mt][nt], alo[mt], bhi[nt]);
                    mma8(acc[mt][nt], ahi[mt], blo[nt]);
                }
        }

        if (kt + 1 < KT) sstore((kt + 1) & 1);
        __syncthreads();
    }

    // epilogue: c0:(g,2tg) c1:(g,2tg+1) c2:(g+8,2tg) c3:(g+8,2tg+1)
#pragma unroll
    for (int mt = 0; mt < 4; ++mt) {
#pragma unroll
        for (int nt = 0; nt < 4; ++nt) {
            const int r0 = m0 + wm * 64 + mt * 16 + g;
            const int c0 = n0 + wn * 32 + nt * 8 + 2 * tg;
            float bv0 = 0.f, bv1 = 0.f;
            if (bias) { bv0 = bias[c0]; bv1 = bias[c0 + 1]; }
            float v00 = acc[mt][nt][0] + bv0;
            float v01 = acc[mt][nt][1] + bv1;
            float v10 = acc[mt][nt][2] + bv0;
            float v11 = acc[mt][nt][3] + bv1;
            if (EPI_COS) {
                v00 = cosf(v00); v01 = cosf(v01);
                v10 = cosf(v10); v11 = cosf(v11);
            }
            *(float2*)(C + (long)r0 * N + c0)       = make_float2(v00, v01);
            *(float2*)(C + (long)(r0 + 8) * N + c0) = make_float2(v10, v11);
        }
    }
}

// ---------------------------------------------------------------------------
// bkr[r] = br[r] + sum_d bk[d] * Wr[d, r]   (one block of 128 threads per r)
__global__ void bkr_kernel(const float* __restrict__ bk,
                           const float* __restrict__ Wr,
                           const float* __restrict__ br,
                           float* __restrict__ bkr, int D)
{
    const int r = blockIdx.x;
    const int t = threadIdx.x;
    float s = 0.f;
    for (int d = t; d < D; d += 128)
        s += bk[d] * Wr[(long)d * D + r];
#pragma unroll
    for (int o = 16; o > 0; o >>= 1) s += __shfl_xor_sync(0xffffffffu, s, o);
    __shared__ float red[4];
    if ((t & 31) == 0) red[t >> 5] = s;
    __syncthreads();
    if (t == 0) bkr[r] = red[0] + red[1] + red[2] + red[3] + br[r];
}

// ---------------------------------------------------------------------------
// Row softmax over 2048 cols, one block (256 threads) per row.
__global__ void softmax_rows(float* __restrict__ scores)
{
    const int NCOL = S_;
    float* p = scores + (long)blockIdx.x * NCOL;
    const int t = threadIdx.x;

    __shared__ float red[32];

    float v[NCOL / 256];
#pragma unroll
    for (int i = 0; i < NCOL / 256; ++i) v[i] = p[t + i * 256];

    float mx = v[0];
#pragma unroll
    for (int i = 1; i < NCOL / 256; ++i) mx = fmaxf(mx, v[i]);
#pragma unroll
    for (int o = 16; o > 0; o >>= 1) mx = fmaxf(mx, __shfl_xor_sync(0xffffffffu, mx, o));
    if ((t & 31) == 0) red[t >> 5] = mx;
    __syncthreads();
    if (t == 0) {
        float m = red[0];
        for (int i = 1; i < 8; ++i) m = fmaxf(m, red[i]);
        red[0] = m;
    }
    __syncthreads();
    mx = red[0];

    float s = 0.f;
#pragma unroll
    for (int i = 0; i < NCOL / 256; ++i) { v[i] = expf(v[i] - mx); s += v[i]; }
#pragma unroll
    for (int o = 16; o > 0; o >>= 1) s += __shfl_xor_sync(0xffffffffu, s, o);
    __syncthreads();
    if ((t & 31) == 0) red[t >> 5] = s;
    __syncthreads();
    if (t == 0) {
        float ss = 0.f;
        for (int i = 0; i < 8; ++i) ss += red[i];
        red[0] = 1.f / ss;
    }
    __syncthreads();
    const float inv = red[0];

#pragma unroll
    for (int i = 0; i < NCOL / 256; ++i) p[t + i * 256] = v[i] * inv;
}

// ---------------------------------------------------------------------------
extern "C" void kernel_launch(void* const* d_in, const int* in_sizes, int n_in,
                              void* d_out, int out_size)
{
    const float* x  = (const float*)d_in[0];
    const float* y  = (const float*)d_in[1];
    const float* Wq = (const float*)d_in[2];
    const float* bq = (const float*)d_in[3];
    const float* Wk = (const float*)d_in[4];
    const float* bk = (const float*)d_in[5];
    const float* Wv = (const float*)d_in[6];
    const float* bv = (const float*)d_in[7];
    const float* Wr = (const float*)d_in[8];
    const float* br = (const float*)d_in[9];
    float* out = (float*)d_out;

    float *Q, *Kh, *V, *Sc, *Wkr, *bkr;
    cudaGetSymbolAddress((void**)&Q,   g_Q);
    cudaGetSymbolAddress((void**)&Kh,  g_Kh);
    cudaGetSymbolAddress((void**)&V,   g_V);
    cudaGetSymbolAddress((void**)&Sc,  g_S);
    cudaGetSymbolAddress((void**)&Wkr, g_Wkr);
    cudaGetSymbolAddress((void**)&bkr, g_bkr);

    // 1) bkr = bk @ Wr + br
    bkr_kernel<<<D_, 128>>>(bk, Wr, br, bkr, D_);

    // 2) Wkr = Wk @ Wr  (1024x1024x1024)
    {
        dim3 g(D_ / 128, D_ / 128, 1);
        mma_gemm<0, 0><<<g, 256>>>(Wk, Wr, nullptr, Wkr, D_, D_, D_, 0, 0, 0);
    }

    // 3) Q = x @ Wq + bq   (8192 x 1024 x 1024)
    {
        dim3 g(D_ / 128, BS_ / 128, 1);
        mma_gemm<0, 0><<<g, 256>>>(x, Wq, bq, Q, BS_, D_, D_, 0, 0, 0);
    }

    // 4) Kh = cos(y @ Wkr + bkr)
    {
        dim3 g(D_ / 128, BS_ / 128, 1);
        mma_gemm<1, 0><<<g, 256>>>(y, Wkr, bkr, Kh, BS_, D_, D_, 0, 0, 0);
    }

    // 5) V = y @ Wv + bv
    {
        dim3 g(D_ / 128, BS_ / 128, 1);
        mma_gemm<0, 0><<<g, 256>>>(y, Wv, bv, V, BS_, D_, D_, 0, 0, 0);
    }

    // 6) scores[b] = Q[b] @ Kh[b]^T   (2048 x 2048 x 1024, batched)
    {
        dim3 g(S_ / 128, S_ / 128, B_);
        mma_gemm<0, 1><<<g, 256>>>(Q, Kh, nullptr, Sc, S_, S_, D_,
                                   (long)S_ * D_, (long)S_ * D_, (long)S_ * S_);
    }

    // 7) softmax rows (in place)
    softmax_rows<<<B_ * S_, 256>>>(Sc);

    // 8) out[b] = probs[b] @ V[b]   (2048 x 1024 x 2048, batched)
    {
        dim3 g(D_ / 128, S_ / 128, B_);
        mma_gemm<0, 0><<<g, 256>>>(Sc, V, nullptr, out, S_, D_, S_,
                                   (long)S_ * S_, (long)S_ * D_, (long)S_ * D_);
    }
}

// round 5
// speedup vs baseline: 2.8103x; 2.0359x over previous
#include <cuda_runtime.h>
#include <cuda_fp16.h>
#include <cstdint>
#include <math.h>

// Problem constants
#define B_  4
#define S_  2048
#define D_  1024
#define BS_ (B_ * S_)          // 8192

// ---------------- scratch (static device globals; no runtime allocation) ----
__device__ float g_Q[BS_ * D_];        // 32 MB
__device__ float g_Kh[BS_ * D_];       // 32 MB
__device__ float g_V[BS_ * D_];        // 32 MB
__device__ float g_VT[BS_ * D_];       // 32 MB (per-batch transposed V)
__device__ float g_S[B_ * S_ * S_];    // 64 MB  (scores / probs in place)
__device__ float g_Wkr[D_ * D_];       // 4 MB
__device__ float g_WkrT[D_ * D_];      // 4 MB
__device__ float g_WqT[D_ * D_];       // 4 MB
__device__ float g_WvT[D_ * D_];       // 4 MB
__device__ float g_WrT[D_ * D_];       // 4 MB
__device__ float g_bkr[D_];

// ===========================================================================
__device__ __forceinline__ uint32_t h2_as_u32(__half2 h) {
    union { __half2 h; uint32_t u; } cvt;
    cvt.h = h;
    return cvt.u;
}

__device__ __forceinline__ void mma16(float* d, const uint32_t* a, const uint32_t* b) {
    asm volatile(
        "mma.sync.aligned.m16n8k16.row.col.f32.f16.f16.f32 "
        "{%0,%1,%2,%3}, {%4,%5,%6,%7}, {%8,%9}, {%0,%1,%2,%3};"
        : "+f"(d[0]), "+f"(d[1]), "+f"(d[2]), "+f"(d[3])
        : "r"(a[0]), "r"(a[1]), "r"(a[2]), "r"(a[3]),
          "r"(b[0]), "r"(b[1]));
}

// split a float4 into hi/lo half2 pairs (Markidis): x = hi + lo, residual ~2^-22
__device__ __forceinline__ void split4(float4 v, uint2& hi, uint2& lo) {
    __half2 h0 = __floats2half2_rn(v.x, v.y);
    __half2 h1 = __floats2half2_rn(v.z, v.w);
    __half2 l0 = __floats2half2_rn(v.x - __low2float(h0), v.y - __high2float(h0));
    __half2 l1 = __floats2half2_rn(v.z - __low2float(h1), v.w - __high2float(h1));
    hi.x = h2_as_u32(h0); hi.y = h2_as_u32(h1);
    lo.x = h2_as_u32(l0); lo.y = h2_as_u32(l1);
}

// ===========================================================================
// fp32 GEMM via fp16 hi/lo split (3 products), tensor cores (m16n8k16).
// C[M,N] = op(A[M,K] @ B[N,K]^T + bias), op = identity or cosf.
// Block tile 128x128, BK=16, 8 warps (2M x 4N), warp tile 64x32, double buffer.
// Conversion fp32->2xfp16 happens ONCE per element at smem-store time.
// M, N divisible by 128; K divisible by 16.
// ===========================================================================
#define PITCH 12   // 24 halves per k-row (16 data + 8 pad) = 12 words

template<int EPI_COS>
__global__ __launch_bounds__(256, 2)
void gemm16(const float* __restrict__ A, const float* __restrict__ Bm,
            const float* __restrict__ bias, float* __restrict__ C,
            int M, int N, int K, long sA, long sB, long sC)
{
    __shared__ uint32_t AsH[2][128][PITCH];   // 12 KB
    __shared__ uint32_t AsL[2][128][PITCH];   // 12 KB
    __shared__ uint32_t BsH[2][128][PITCH];   // 12 KB
    __shared__ uint32_t BsL[2][128][PITCH];   // 12 KB

    A  += (long)blockIdx.z * sA;
    Bm += (long)blockIdx.z * sB;
    C  += (long)blockIdx.z * sC;

    const int m0 = blockIdx.y * 128;
    const int n0 = blockIdx.x * 128;
    const int t    = threadIdx.x;
    const int lane = t & 31;
    const int w    = t >> 5;
    const int g    = lane >> 2;   // 0..7
    const int tg   = lane & 3;    // 0..3
    const int wm   = w & 1;
    const int wn   = w >> 1;

    // producer mapping: row pair (r, r+64), 4 consecutive k per thread
    const int p_r = t >> 2;          // 0..63
    const int p_c = (t & 3) * 4;     // k offset 0/4/8/12
    const int p_w = (t & 3) * 2;     // word offset in pitched row

    float4 pa0, pa1, pb0, pb1;

    auto gload = [&](int kt) {
        const float* Ap = A + (long)(m0 + p_r) * K + kt * 16 + p_c;
        pa0 = *(const float4*)Ap;
        pa1 = *(const float4*)(Ap + 64L * K);
        const float* Bp = Bm + (long)(n0 + p_r) * K + kt * 16 + p_c;
        pb0 = *(const float4*)Bp;
        pb1 = *(const float4*)(Bp + 64L * K);
    };

    auto sstore = [&](int buf) {
        uint2 hi, lo;
        split4(pa0, hi, lo);
        *(uint2*)&AsH[buf][p_r][p_w] = hi;      *(uint2*)&AsL[buf][p_r][p_w] = lo;
        split4(pa1, hi, lo);
        *(uint2*)&AsH[buf][p_r + 64][p_w] = hi; *(uint2*)&AsL[buf][p_r + 64][p_w] = lo;
        split4(pb0, hi, lo);
        *(uint2*)&BsH[buf][p_r][p_w] = hi;      *(uint2*)&BsL[buf][p_r][p_w] = lo;
        split4(pb1, hi, lo);
        *(uint2*)&BsH[buf][p_r + 64][p_w] = hi; *(uint2*)&BsL[buf][p_r + 64][p_w] = lo;
    };

    float acc[4][4][4];
#pragma unroll
    for (int i = 0; i < 4; ++i)
#pragma unroll
        for (int j = 0; j < 4; ++j)
#pragma unroll
            for (int r = 0; r < 4; ++r) acc[i][j][r] = 0.f;

    const int KT = K / 16;
    gload(0);
    sstore(0);
    __syncthreads();

    const int arow = wm * 64 + g;
    const int brow = wn * 32 + g;

    for (int kt = 0; kt < KT; ++kt) {
        const int cur = kt & 1;
        if (kt + 1 < KT) gload(kt + 1);

        uint32_t bh[4][2], bl[4][2];
#pragma unroll
        for (int nt = 0; nt < 4; ++nt) {
            const int br = brow + nt * 8;
            bh[nt][0] = BsH[cur][br][tg];
            bh[nt][1] = BsH[cur][br][tg + 4];
            bl[nt][0] = BsL[cur][br][tg];
            bl[nt][1] = BsL[cur][br][tg + 4];
        }
#pragma unroll
        for (int mt = 0; mt < 4; ++mt) {
            const int ar = arow + mt * 16;
            uint32_t ah[4], al[4];
            ah[0] = AsH[cur][ar][tg];     ah[1] = AsH[cur][ar + 8][tg];
            ah[2] = AsH[cur][ar][tg + 4]; ah[3] = AsH[cur][ar + 8][tg + 4];
            al[0] = AsL[cur][ar][tg];     al[1] = AsL[cur][ar + 8][tg];
            al[2] = AsL[cur][ar][tg + 4]; al[3] = AsL[cur][ar + 8][tg + 4];
#pragma unroll
            for (int nt = 0; nt < 4; ++nt) {
                mma16(acc[mt][nt], ah, bh[nt]);
                mma16(acc[mt][nt], al, bh[nt]);
                mma16(acc[mt][nt], ah, bl[nt]);
            }
        }

        if (kt + 1 < KT) sstore((kt + 1) & 1);
        __syncthreads();
    }

    // epilogue: c0:(g,2tg) c1:(g,2tg+1) c2:(g+8,2tg) c3:(g+8,2tg+1)
#pragma unroll
    for (int mt = 0; mt < 4; ++mt) {
#pragma unroll
        for (int nt = 0; nt < 4; ++nt) {
            const int r0 = m0 + wm * 64 + mt * 16 + g;
            const int c0 = n0 + wn * 32 + nt * 8 + 2 * tg;
            float bv0 = 0.f, bv1 = 0.f;
            if (bias) { bv0 = bias[c0]; bv1 = bias[c0 + 1]; }
            float v00 = acc[mt][nt][0] + bv0;
            float v01 = acc[mt][nt][1] + bv1;
            float v10 = acc[mt][nt][2] + bv0;
            float v11 = acc[mt][nt][3] + bv1;
            if (EPI_COS) {
                v00 = cosf(v00); v01 = cosf(v01);
                v10 = cosf(v10); v11 = cosf(v11);
            }
            *(float2*)(C + (long)r0 * N + c0)       = make_float2(v00, v01);
            *(float2*)(C + (long)(r0 + 8) * N + c0) = make_float2(v10, v11);
        }
    }
}

// ===========================================================================
// Tiled transpose: dst[z][c][r] = src[z][r][c]; R, C divisible by 32
// ===========================================================================
__global__ void transpose_k(const float* __restrict__ src, float* __restrict__ dst,
                            int R, int C)
{
    __shared__ float tile[32][33];
    const long zo = (long)blockIdx.z * R * C;
    const int c0 = blockIdx.x * 32, r0 = blockIdx.y * 32;
    const int x = threadIdx.x, y = threadIdx.y;   // 32 x 8
#pragma unroll
    for (int j = 0; j < 32; j += 8)
        tile[y + j][x] = src[zo + (long)(r0 + y + j) * C + c0 + x];
    __syncthreads();
#pragma unroll
    for (int j = 0; j < 32; j += 8)
        dst[zo + (long)(c0 + y + j) * R + r0 + x] = tile[x][y + j];
}

// ---------------------------------------------------------------------------
// bkr[r] = br[r] + sum_d bk[d] * Wr[d, r]
__global__ void bkr_kernel(const float* __restrict__ bk,
                           const float* __restrict__ Wr,
                           const float* __restrict__ br,
                           float* __restrict__ bkr, int D)
{
    const int r = blockIdx.x;
    const int t = threadIdx.x;
    float s = 0.f;
    for (int d = t; d < D; d += 128)
        s += bk[d] * Wr[(long)d * D + r];
#pragma unroll
    for (int o = 16; o > 0; o >>= 1) s += __shfl_xor_sync(0xffffffffu, s, o);
    __shared__ float red[4];
    if ((t & 31) == 0) red[t >> 5] = s;
    __syncthreads();
    if (t == 0) bkr[r] = red[0] + red[1] + red[2] + red[3] + br[r];
}

// ---------------------------------------------------------------------------
// Row softmax over 2048 cols, one block (256 threads) per row.
__global__ void softmax_rows(float* __restrict__ scores)
{
    const int NCOL = S_;
    float* p = scores + (long)blockIdx.x * NCOL;
    const int t = threadIdx.x;

    __shared__ float red[32];

    float v[NCOL / 256];
#pragma unroll
    for (int i = 0; i < NCOL / 256; ++i) v[i] = p[t + i * 256];

    float mx = v[0];
#pragma unroll
    for (int i = 1; i < NCOL / 256; ++i) mx = fmaxf(mx, v[i]);
#pragma unroll
    for (int o = 16; o > 0; o >>= 1) mx = fmaxf(mx, __shfl_xor_sync(0xffffffffu, mx, o));
    if ((t & 31) == 0) red[t >> 5] = mx;
    __syncthreads();
    if (t == 0) {
        float m = red[0];
        for (int i = 1; i < 8; ++i) m = fmaxf(m, red[i]);
        red[0] = m;
    }
    __syncthreads();
    mx = red[0];

    float s = 0.f;
#pragma unroll
    for (int i = 0; i < NCOL / 256; ++i) { v[i] = expf(v[i] - mx); s += v[i]; }
#pragma unroll
    for (int o = 16; o > 0; o >>= 1) s += __shfl_xor_sync(0xffffffffu, s, o);
    __syncthreads();
    if ((t & 31) == 0) red[t >> 5] = s;
    __syncthreads();
    if (t == 0) {
        float ss = 0.f;
        for (int i = 0; i < 8; ++i) ss += red[i];
        red[0] = 1.f / ss;
    }
    __syncthreads();
    const float inv = red[0];

#pragma unroll
    for (int i = 0; i < NCOL / 256; ++i) p[t + i * 256] = v[i] * inv;
}

// ---------------------------------------------------------------------------
extern "C" void kernel_launch(void* const* d_in, const int* in_sizes, int n_in,
                              void* d_out, int out_size)
{
    const float* x  = (const float*)d_in[0];
    const float* y  = (const float*)d_in[1];
    const float* Wq = (const float*)d_in[2];
    const float* bq = (const float*)d_in[3];
    const float* Wk = (const float*)d_in[4];
    const float* bk = (const float*)d_in[5];
    const float* Wv = (const float*)d_in[6];
    const float* bv = (const float*)d_in[7];
    const float* Wr = (const float*)d_in[8];
    const float* br = (const float*)d_in[9];
    float* out = (float*)d_out;

    float *Q, *Kh, *V, *VT, *Sc, *Wkr, *WkrT, *WqT, *WvT, *WrT, *bkr;
    cudaGetSymbolAddress((void**)&Q,    g_Q);
    cudaGetSymbolAddress((void**)&Kh,   g_Kh);
    cudaGetSymbolAddress((void**)&V,    g_V);
    cudaGetSymbolAddress((void**)&VT,   g_VT);
    cudaGetSymbolAddress((void**)&Sc,   g_S);
    cudaGetSymbolAddress((void**)&Wkr,  g_Wkr);
    cudaGetSymbolAddress((void**)&WkrT, g_WkrT);
    cudaGetSymbolAddress((void**)&WqT,  g_WqT);
    cudaGetSymbolAddress((void**)&WvT,  g_WvT);
    cudaGetSymbolAddress((void**)&WrT,  g_WrT);
    cudaGetSymbolAddress((void**)&bkr,  g_bkr);

    dim3 tb(32, 8);

    // 0) bkr = bk @ Wr + br
    bkr_kernel<<<D_, 128>>>(bk, Wr, br, bkr, D_);

    // 1) transposes of weights (B operand must be [N][K] k-major)
    {
        dim3 g(D_ / 32, D_ / 32, 1);
        transpose_k<<<g, tb>>>(Wr, WrT, D_, D_);
        transpose_k<<<g, tb>>>(Wq, WqT, D_, D_);
        transpose_k<<<g, tb>>>(Wv, WvT, D_, D_);
    }

    // 2) Wkr = Wk @ Wr = Wk @ (WrT)^T
    {
        dim3 g(D_ / 128, D_ / 128, 1);
        gemm16<0><<<g, 256>>>(Wk, WrT, nullptr, Wkr, D_, D_, D_, 0, 0, 0);
    }
    {
        dim3 g(D_ / 32, D_ / 32, 1);
        transpose_k<<<g, tb>>>(Wkr, WkrT, D_, D_);
    }

    // 3) Q = x @ (WqT)^T + bq
    {
        dim3 g(D_ / 128, BS_ / 128, 1);
        gemm16<0><<<g, 256>>>(x, WqT, bq, Q, BS_, D_, D_, 0, 0, 0);
    }

    // 4) Kh = cos(y @ (WkrT)^T + bkr)
    {
        dim3 g(D_ / 128, BS_ / 128, 1);
        gemm16<1><<<g, 256>>>(y, WkrT, bkr, Kh, BS_, D_, D_, 0, 0, 0);
    }

    // 5) V = y @ (WvT)^T + bv
    {
        dim3 g(D_ / 128, BS_ / 128, 1);
        gemm16<0><<<g, 256>>>(y, WvT, bv, V, BS_, D_, D_, 0, 0, 0);
    }

    // 6) VT[b] = V[b]^T   ([S,D] -> [D,S] per batch)
    {
        dim3 g(D_ / 32, S_ / 32, B_);
        transpose_k<<<g, tb>>>(V, VT, S_, D_);
    }

    // 7) scores[b] = Q[b] @ Kh[b]^T
    {
        dim3 g(S_ / 128, S_ / 128, B_);
        gemm16<0><<<g, 256>>>(Q, Kh, nullptr, Sc, S_, S_, D_,
                              (long)S_ * D_, (long)S_ * D_, (long)S_ * S_);
    }

    // 8) softmax rows (in place)
    softmax_rows<<<B_ * S_, 256>>>(Sc);

    // 9) out[b] = probs[b] @ (VT[b])^T
    {
        dim3 g(D_ / 128, S_ / 128, B_);
        gemm16<0><<<g, 256>>>(Sc, VT, nullptr, out, S_, D_, S_,
                              (long)S_ * S_, (long)S_ * D_, (long)S_ * D_);
    }
}

// round 6
// speedup vs baseline: 3.0932x; 1.1007x over previous
#include <cuda_runtime.h>
#include <cuda_fp16.h>
#include <cstdint>
#include <math.h>

// Problem constants
#define B_  4
#define S_  2048
#define D_  1024
#define BS_ (B_ * S_)          // 8192

// ---------------- scratch (static device globals; no runtime allocation) ----
__device__ __half g_Xh[BS_ * D_], g_Xl[BS_ * D_];        // x hi/lo
__device__ __half g_Yh[BS_ * D_], g_Yl[BS_ * D_];        // y hi/lo
__device__ __half g_Qh[BS_ * D_], g_Ql[BS_ * D_];        // Q hi/lo
__device__ __half g_Khh[BS_ * D_], g_Khl[BS_ * D_];      // Kh hi/lo
__device__ __half g_VTh[BS_ * D_], g_VTl[BS_ * D_];      // V^T per batch hi/lo
__device__ __half g_Ph[B_ * S_ * S_], g_Pl[B_ * S_ * S_];// probs hi/lo
__device__ __half g_WrTh[D_ * D_], g_WrTl[D_ * D_];
__device__ __half g_WqTh[D_ * D_], g_WqTl[D_ * D_];
__device__ __half g_WvTh[D_ * D_], g_WvTl[D_ * D_];
__device__ __half g_Wkh[D_ * D_], g_Wkl[D_ * D_];
__device__ __half g_WkrTh[D_ * D_], g_WkrTl[D_ * D_];
__device__ float  g_V[BS_ * D_];       // V fp32 (pre-transpose)
__device__ float  g_S[B_ * S_ * S_];   // scores fp32
__device__ float  g_bkr[D_];

// ===========================================================================
__device__ __forceinline__ uint32_t h2u(__half2 h) {
    union { __half2 h; uint32_t u; } c; c.h = h; return c.u;
}

__device__ __forceinline__ void mma16(float* d, const uint32_t* a, const uint32_t* b) {
    asm volatile(
        "mma.sync.aligned.m16n8k16.row.col.f32.f16.f16.f32 "
        "{%0,%1,%2,%3}, {%4,%5,%6,%7}, {%8,%9}, {%0,%1,%2,%3};"
        : "+f"(d[0]), "+f"(d[1]), "+f"(d[2]), "+f"(d[3])
        : "r"(a[0]), "r"(a[1]), "r"(a[2]), "r"(a[3]),
          "r"(b[0]), "r"(b[1]));
}

__device__ __forceinline__ void cpa16(uint32_t dst, const void* src) {
    asm volatile("cp.async.cg.shared.global [%0], [%1], 16;" :: "r"(dst), "l"(src));
}
__device__ __forceinline__ void cpa_commit() {
    asm volatile("cp.async.commit_group;" ::: "memory");
}
__device__ __forceinline__ uint32_t smem_u32(const void* p) {
    uint32_t a;
    asm("{ .reg .u64 t; cvta.to.shared.u64 t, %1; cvt.u32.u64 %0, t; }"
        : "=r"(a) : "l"(p));
    return a;
}

// ===========================================================================
// Pure-fp16 3-product GEMM (Markidis):  C[M,N] = op(A @ B^T + bias)
// A given as hi/lo half [M,K] row-major; B as hi/lo half [N,K] row-major.
// 128x128 block tile, BK=32, 3-stage cp.async pipeline, XOR-swizzled smem.
// 8 warps (2M x 4N), warp tile 64x32. M,N div 128; K div 32.
// OUT_HALF: write hi/lo half pair instead of fp32.
// ===========================================================================
#define ARR_HALFS   (128 * 32)             // 4096 halves = 8KB
#define STAGE_HALFS (4 * ARR_HALFS)        // Ah, Al, Bh, Bl
#define GSM_BYTES   (3 * STAGE_HALFS * 2)  // 96KB

template<int EPI_COS, int OUT_HALF>
__global__ __launch_bounds__(256, 2)
void gemmh(const __half* __restrict__ Ah, const __half* __restrict__ Al,
           const __half* __restrict__ Bh, const __half* __restrict__ Bl,
           const float* __restrict__ bias,
           float* __restrict__ C, __half* __restrict__ Ch, __half* __restrict__ Cl,
           int M, int N, int K, long sA, long sB, long sC)
{
    extern __shared__ __half sm[];
    const uint32_t smb = smem_u32(sm);

    Ah += (long)blockIdx.z * sA;  Al += (long)blockIdx.z * sA;
    Bh += (long)blockIdx.z * sB;  Bl += (long)blockIdx.z * sB;

    const int m0 = blockIdx.y * 128;
    const int n0 = blockIdx.x * 128;
    const int t    = threadIdx.x;
    const int lane = t & 31;
    const int w    = t >> 5;
    const int g    = lane >> 2;   // 0..7
    const int tg   = lane & 3;    // 0..3
    const int wm   = w & 1;
    const int wn   = w >> 1;

    const int KT = K / 32;

    // ---- producer: 8 cp.async of 16B per thread per stage ----
    auto stage_load = [&](int s, int kt) {
        const long kb = (long)kt * 32;
#pragma unroll
        for (int h = 0; h < 2; ++h) {
            const int c   = t + h * 256;          // 0..511
            const int row = c >> 2, q = c & 3;
            const int pq  = q ^ ((row >> 1) & 3);
            const uint32_t so = smb + (uint32_t)(s * STAGE_HALFS + row * 32 + pq * 8) * 2;
            const long ga = (long)(m0 + row) * K + kb + q * 8;
            const long gb = (long)(n0 + row) * K + kb + q * 8;
            cpa16(so,                     Ah + ga);
            cpa16(so + ARR_HALFS * 2,     Al + ga);
            cpa16(so + ARR_HALFS * 4,     Bh + gb);
            cpa16(so + ARR_HALFS * 6,     Bl + gb);
        }
        cpa_commit();
    };

    // swizzled word load: row 0..127, word w16 0..15 within 32-half row
    auto ldw = [&](const __half* base, int row, int w16) -> uint32_t {
        const int pg = (w16 >> 2) ^ ((row >> 1) & 3);
        return *(const uint32_t*)(base + row * 32 + ((pg << 2) | (w16 & 3)) * 2);
    };

    float acc[4][4][4];
#pragma unroll
    for (int i = 0; i < 4; ++i)
#pragma unroll
        for (int j = 0; j < 4; ++j)
#pragma unroll
            for (int r = 0; r < 4; ++r) acc[i][j][r] = 0.f;

    stage_load(0, 0);
    stage_load(1, 1);

    const int arow = wm * 64 + g;
    const int brow = wn * 32 + g;

    for (int kt = 0; kt < KT; ++kt) {
        asm volatile("cp.async.wait_group 1;" ::: "memory");
        __syncthreads();
        if (kt + 2 < KT) stage_load((kt + 2) % 3, kt + 2);

        const __half* sAh = sm + (kt % 3) * STAGE_HALFS;
        const __half* sAl = sAh + ARR_HALFS;
        const __half* sBh = sAh + 2 * ARR_HALFS;
        const __half* sBl = sAh + 3 * ARR_HALFS;

#pragma unroll
        for (int ks = 0; ks < 2; ++ks) {
            const int w0 = tg + 8 * ks;       // group 2ks
            const int w1 = tg + 4 + 8 * ks;   // group 2ks+1

            uint32_t bh[4][2], bl[4][2];
#pragma unroll
            for (int nt = 0; nt < 4; ++nt) {
                const int br = brow + nt * 8;
                bh[nt][0] = ldw(sBh, br, w0); bh[nt][1] = ldw(sBh, br, w1);
                bl[nt][0] = ldw(sBl, br, w0); bl[nt][1] = ldw(sBl, br, w1);
            }
#pragma unroll
            for (int mt = 0; mt < 4; ++mt) {
                const int ar = arow + mt * 16;
                uint32_t ah[4], al[4];
                ah[0] = ldw(sAh, ar, w0);     ah[1] = ldw(sAh, ar + 8, w0);
                ah[2] = ldw(sAh, ar, w1);     ah[3] = ldw(sAh, ar + 8, w1);
                al[0] = ldw(sAl, ar, w0);     al[1] = ldw(sAl, ar + 8, w0);
                al[2] = ldw(sAl, ar, w1);     al[3] = ldw(sAl, ar + 8, w1);
#pragma unroll
                for (int nt = 0; nt < 4; ++nt) {
                    mma16(acc[mt][nt], ah, bh[nt]);
                    mma16(acc[mt][nt], al, bh[nt]);
                    mma16(acc[mt][nt], ah, bl[nt]);
                }
            }
        }
    }

    // epilogue: c0:(g,2tg) c1:(g,2tg+1) c2:(g+8,2tg) c3:(g+8,2tg+1)
#pragma unroll
    for (int mt = 0; mt < 4; ++mt) {
#pragma unroll
        for (int nt = 0; nt < 4; ++nt) {
            const int r0 = m0 + wm * 64 + mt * 16 + g;
            const int c0 = n0 + wn * 32 + nt * 8 + 2 * tg;
            float bv0 = 0.f, bv1 = 0.f;
            if (bias) { bv0 = bias[c0]; bv1 = bias[c0 + 1]; }
            float v00 = acc[mt][nt][0] + bv0;
            float v01 = acc[mt][nt][1] + bv1;
            float v10 = acc[mt][nt][2] + bv0;
            float v11 = acc[mt][nt][3] + bv1;
            if (EPI_COS) {
                v00 = cosf(v00); v01 = cosf(v01);
                v10 = cosf(v10); v11 = cosf(v11);
            }
            if (OUT_HALF) {
                __half2 h0 = __floats2half2_rn(v00, v01);
                __half2 h1 = __floats2half2_rn(v10, v11);
                __half2 l0 = __floats2half2_rn(v00 - __low2float(h0), v01 - __high2float(h0));
                __half2 l1 = __floats2half2_rn(v10 - __low2float(h1), v11 - __high2float(h1));
                long o0 = (long)blockIdx.z * sC + (long)r0 * N + c0;
                long o1 = o0 + 8L * N;
                *(uint32_t*)(Ch + o0) = h2u(h0);
                *(uint32_t*)(Cl + o0) = h2u(l0);
                *(uint32_t*)(Ch + o1) = h2u(h1);
                *(uint32_t*)(Cl + o1) = h2u(l1);
            } else {
                long o0 = (long)blockIdx.z * sC + (long)r0 * N + c0;
                *(float2*)(C + o0)          = make_float2(v00, v01);
                *(float2*)(C + o0 + 8L * N) = make_float2(v10, v11);
            }
        }
    }
}

// ===========================================================================
// Elementwise fp32 -> (hi,lo) fp16 convert. n divisible by 1024.
// ===========================================================================
__global__ void conv_hl(const float* __restrict__ src,
                        __half* __restrict__ h, __half* __restrict__ l)
{
    const long i = ((long)blockIdx.x * 256 + threadIdx.x) * 4;
    float4 v = *(const float4*)(src + i);
    __half2 h0 = __floats2half2_rn(v.x, v.y);
    __half2 h1 = __floats2half2_rn(v.z, v.w);
    __half2 l0 = __floats2half2_rn(v.x - __low2float(h0), v.y - __high2float(h0));
    __half2 l1 = __floats2half2_rn(v.z - __low2float(h1), v.w - __high2float(h1));
    *(uint2*)(h + i) = make_uint2(h2u(h0), h2u(h1));
    *(uint2*)(l + i) = make_uint2(h2u(l0), h2u(l1));
}

// ===========================================================================
// Transpose + convert: dst_{h,l}[z][c][r] = split(src[z][r][c]); R,C div 32
// ===========================================================================
__global__ void convT_hl(const float* __restrict__ src,
                         __half* __restrict__ dh, __half* __restrict__ dl,
                         int R, int C)
{
    __shared__ float tile[32][33];
    const long zo = (long)blockIdx.z * R * C;
    const int c0 = blockIdx.x * 32, r0 = blockIdx.y * 32;
    const int x = threadIdx.x, y = threadIdx.y;   // 32 x 8
#pragma unroll
    for (int j = 0; j < 32; j += 8)
        tile[y + j][x] = src[zo + (long)(r0 + y + j) * C + c0 + x];
    __syncthreads();
#pragma unroll
    for (int j = 0; j < 32; j += 8) {
        float v = tile[x][y + j];
        __half hh = __float2half_rn(v);
        long o = zo + (long)(c0 + y + j) * R + r0 + x;
        dh[o] = hh;
        dl[o] = __float2half_rn(v - __half2float(hh));
    }
}

// ---------------------------------------------------------------------------
// bkr[r] = br[r] + sum_d bk[d] * Wr[d, r]
__global__ void bkr_kernel(const float* __restrict__ bk,
                           const float* __restrict__ Wr,
                           const float* __restrict__ br,
                           float* __restrict__ bkr, int D)
{
    const int r = blockIdx.x;
    const int t = threadIdx.x;
    float s = 0.f;
    for (int d = t; d < D; d += 128)
        s += bk[d] * Wr[(long)d * D + r];
#pragma unroll
    for (int o = 16; o > 0; o >>= 1) s += __shfl_xor_sync(0xffffffffu, s, o);
    __shared__ float red[4];
    if ((t & 31) == 0) red[t >> 5] = s;
    __syncthreads();
    if (t == 0) bkr[r] = red[0] + red[1] + red[2] + red[3] + br[r];
}

// ---------------------------------------------------------------------------
// Row softmax over 2048 cols; writes probs as hi/lo half pair.
__global__ void softmax_rows(const float* __restrict__ scores,
                             __half* __restrict__ ph, __half* __restrict__ pl)
{
    const int NCOL = S_;
    const float* p = scores + (long)blockIdx.x * NCOL;
    const int t = threadIdx.x;

    __shared__ float red[32];

    float v[NCOL / 256];
#pragma unroll
    for (int i = 0; i < NCOL / 256; ++i) v[i] = p[t + i * 256];

    float mx = v[0];
#pragma unroll
    for (int i = 1; i < NCOL / 256; ++i) mx = fmaxf(mx, v[i]);
#pragma unroll
    for (int o = 16; o > 0; o >>= 1) mx = fmaxf(mx, __shfl_xor_sync(0xffffffffu, mx, o));
    if ((t & 31) == 0) red[t >> 5] = mx;
    __syncthreads();
    if (t == 0) {
        float m = red[0];
        for (int i = 1; i < 8; ++i) m = fmaxf(m, red[i]);
        red[0] = m;
    }
    __syncthreads();
    mx = red[0];

    float s = 0.f;
#pragma unroll
    for (int i = 0; i < NCOL / 256; ++i) { v[i] = expf(v[i] - mx); s += v[i]; }
#pragma unroll
    for (int o = 16; o > 0; o >>= 1) s += __shfl_xor_sync(0xffffffffu, s, o);
    __syncthreads();
    if ((t & 31) == 0) red[t >> 5] = s;
    __syncthreads();
    if (t == 0) {
        float ss = 0.f;
        for (int i = 0; i < 8; ++i) ss += red[i];
        red[0] = 1.f / ss;
    }
    __syncthreads();
    const float inv = red[0];

    __half* hp = ph + (long)blockIdx.x * NCOL;
    __half* lp = pl + (long)blockIdx.x * NCOL;
#pragma unroll
    for (int i = 0; i < NCOL / 256; ++i) {
        float pv = v[i] * inv;
        __half hh = __float2half_rn(pv);
        hp[t + i * 256] = hh;
        lp[t + i * 256] = __float2half_rn(pv - __half2float(hh));
    }
}

// ---------------------------------------------------------------------------
extern "C" void kernel_launch(void* const* d_in, const int* in_sizes, int n_in,
                              void* d_out, int out_size)
{
    const float* x  = (const float*)d_in[0];
    const float* y  = (const float*)d_in[1];
    const float* Wq = (const float*)d_in[2];
    const float* bq = (const float*)d_in[3];
    const float* Wk = (const float*)d_in[4];
    const float* bk = (const float*)d_in[5];
    const float* Wv = (const float*)d_in[6];
    const float* bv = (const float*)d_in[7];
    const float* Wr = (const float*)d_in[8];
    const float* br = (const float*)d_in[9];
    float* out = (float*)d_out;

    __half *Xh, *Xl, *Yh, *Yl, *Qh, *Ql, *Khh, *Khl, *VTh, *VTl, *Ph, *Pl;
    __half *WrTh, *WrTl, *WqTh, *WqTl, *WvTh, *WvTl, *Wkh, *Wkl, *WkrTh, *WkrTl;
    float *V, *Sc, *bkr;
    cudaGetSymbolAddress((void**)&Xh, g_Xh);   cudaGetSymbolAddress((void**)&Xl, g_Xl);
    cudaGetSymbolAddress((void**)&Yh, g_Yh);   cudaGetSymbolAddress((void**)&Yl, g_Yl);
    cudaGetSymbolAddress((void**)&Qh, g_Qh);   cudaGetSymbolAddress((void**)&Ql, g_Ql);
    cudaGetSymbolAddress((void**)&Khh, g_Khh); cudaGetSymbolAddress((void**)&Khl, g_Khl);
    cudaGetSymbolAddress((void**)&VTh, g_VTh); cudaGetSymbolAddress((void**)&VTl, g_VTl);
    cudaGetSymbolAddress((void**)&Ph, g_Ph);   cudaGetSymbolAddress((void**)&Pl, g_Pl);
    cudaGetSymbolAddress((void**)&WrTh, g_WrTh); cudaGetSymbolAddress((void**)&WrTl, g_WrTl);
    cudaGetSymbolAddress((void**)&WqTh, g_WqTh); cudaGetSymbolAddress((void**)&WqTl, g_WqTl);
    cudaGetSymbolAddress((void**)&WvTh, g_WvTh); cudaGetSymbolAddress((void**)&WvTl, g_WvTl);
    cudaGetSymbolAddress((void**)&Wkh, g_Wkh);   cudaGetSymbolAddress((void**)&Wkl, g_Wkl);
    cudaGetSymbolAddress((void**)&WkrTh, g_WkrTh); cudaGetSymbolAddress((void**)&WkrTl, g_WkrTl);
    cudaGetSymbolAddress((void**)&V, g_V);
    cudaGetSymbolAddress((void**)&Sc, g_S);
    cudaGetSymbolAddress((void**)&bkr, g_bkr);

    cudaFuncSetAttribute(gemmh<0,0>, cudaFuncAttributeMaxDynamicSharedMemorySize, GSM_BYTES);
    cudaFuncSetAttribute(gemmh<0,1>, cudaFuncAttributeMaxDynamicSharedMemorySize, GSM_BYTES);
    cudaFuncSetAttribute(gemmh<1,1>, cudaFuncAttributeMaxDynamicSharedMemorySize, GSM_BYTES);

    dim3 tb(32, 8);

    // 0) bkr = bk @ Wr + br
    bkr_kernel<<<D_, 128>>>(bk, Wr, br, bkr, D_);

    // 1) convert inputs / weights
    conv_hl<<<BS_ * D_ / 1024, 256>>>(x, Xh, Xl);
    conv_hl<<<BS_ * D_ / 1024, 256>>>(y, Yh, Yl);
    conv_hl<<<D_ * D_ / 1024, 256>>>(Wk, Wkh, Wkl);
    {
        dim3 g(D_ / 32, D_ / 32, 1);
        convT_hl<<<g, tb>>>(Wr, WrTh, WrTl, D_, D_);
        convT_hl<<<g, tb>>>(Wq, WqTh, WqTl, D_, D_);
        convT_hl<<<g, tb>>>(Wv, WvTh, WvTl, D_, D_);
    }

    // 2) WkrT = Wr^T @ Wk^T  (A = WrT [r,e], B = Wk [d,e]) -> half pair
    {
        dim3 g(D_ / 128, D_ / 128, 1);
        gemmh<0,1><<<g, 256, GSM_BYTES>>>(WrTh, WrTl, Wkh, Wkl, nullptr,
                                          nullptr, WkrTh, WkrTl, D_, D_, D_, 0, 0, 0);
    }

    // 3) Q = x @ Wq + bq -> half pair
    {
        dim3 g(D_ / 128, BS_ / 128, 1);
        gemmh<0,1><<<g, 256, GSM_BYTES>>>(Xh, Xl, WqTh, WqTl, bq,
                                          nullptr, Qh, Ql, BS_, D_, D_, 0, 0, 0);
    }

    // 4) Kh = cos(y @ Wkr + bkr) -> half pair
    {
        dim3 g(D_ / 128, BS_ / 128, 1);
        gemmh<1,1><<<g, 256, GSM_BYTES>>>(Yh, Yl, WkrTh, WkrTl, bkr,
                                          nullptr, Khh, Khl, BS_, D_, D_, 0, 0, 0);
    }

    // 5) V = y @ Wv + bv -> fp32
    {
        dim3 g(D_ / 128, BS_ / 128, 1);
        gemmh<0,0><<<g, 256, GSM_BYTES>>>(Yh, Yl, WvTh, WvTl, bv,
                                          V, nullptr, nullptr, BS_, D_, D_, 0, 0, 0);
    }

    // 6) VT[b] = split(V[b]^T)  ([S,D] -> [D,S] per batch)
    {
        dim3 g(D_ / 32, S_ / 32, B_);
        convT_hl<<<g, tb>>>(V, VTh, VTl, S_, D_);
    }

    // 7) scores[b] = Q[b] @ Kh[b]^T -> fp32
    {
        dim3 g(S_ / 128, S_ / 128, B_);
        gemmh<0,0><<<g, 256, GSM_BYTES>>>(Qh, Ql, Khh, Khl, nullptr,
                                          Sc, nullptr, nullptr, S_, S_, D_,
                                          (long)S_ * D_, (long)S_ * D_, (long)S_ * S_);
    }

    // 8) softmax rows -> probs half pair
    softmax_rows<<<B_ * S_, 256>>>(Sc, Ph, Pl);

    // 9) out[b] = P[b] @ VT[b]^T -> fp32
    {
        dim3 g(D_ / 128, S_ / 128, B_);
        gemmh<0,0><<<g, 256, GSM_BYTES>>>(Ph, Pl, VTh, VTl, nullptr,
                                          out, nullptr, nullptr, S_, D_, S_,
                                          (long)S_ * S_, (long)D_ * S_, (long)S_ * D_);
    }
}

// round 7
// speedup vs baseline: 3.3641x; 1.0876x over previous
#include <cuda_runtime.h>
#include <cuda_fp16.h>
#include <cstdint>
#include <math.h>

// Problem constants
#define B_  4
#define S_  2048
#define D_  1024
#define BS_ (B_ * S_)          // 8192

// ---------------- scratch (static device globals; no runtime allocation) ----
__device__ __half g_Xh[BS_ * D_], g_Xl[BS_ * D_];        // x hi/lo
__device__ __half g_Yh[BS_ * D_], g_Yl[BS_ * D_];        // y hi/lo
__device__ __half g_Qh[BS_ * D_], g_Ql[BS_ * D_];        // Q hi/lo
__device__ __half g_Khh[BS_ * D_], g_Khl[BS_ * D_];      // Kh hi/lo
__device__ __half g_VTh[BS_ * D_], g_VTl[BS_ * D_];      // V^T per batch hi/lo
__device__ __half g_Ph[B_ * S_ * S_], g_Pl[B_ * S_ * S_];// probs hi/lo
__device__ __half g_WrTh[D_ * D_], g_WrTl[D_ * D_];
__device__ __half g_WqTh[D_ * D_], g_WqTl[D_ * D_];
__device__ __half g_WvTh[D_ * D_], g_WvTl[D_ * D_];
__device__ __half g_Wkh[D_ * D_], g_Wkl[D_ * D_];
__device__ __half g_WkrTh[D_ * D_], g_WkrTl[D_ * D_];
__device__ float  g_V[BS_ * D_];       // V fp32 (pre-transpose)
__device__ float  g_S[B_ * S_ * S_];   // scores fp32
__device__ float  g_bkr[D_];

// ===========================================================================
__device__ __forceinline__ uint32_t h2u(__half2 h) {
    union { __half2 h; uint32_t u; } c; c.h = h; return c.u;
}

__device__ __forceinline__ void mma16(float* d, const uint32_t* a, const uint32_t* b) {
    asm volatile(
        "mma.sync.aligned.m16n8k16.row.col.f32.f16.f16.f32 "
        "{%0,%1,%2,%3}, {%4,%5,%6,%7}, {%8,%9}, {%0,%1,%2,%3};"
        : "+f"(d[0]), "+f"(d[1]), "+f"(d[2]), "+f"(d[3])
        : "r"(a[0]), "r"(a[1]), "r"(a[2]), "r"(a[3]),
          "r"(b[0]), "r"(b[1]));
}

__device__ __forceinline__ void ldsm4(uint32_t* r, uint32_t addr) {
    asm volatile("ldmatrix.sync.aligned.m8n8.x4.shared.b16 {%0,%1,%2,%3}, [%4];"
        : "=r"(r[0]), "=r"(r[1]), "=r"(r[2]), "=r"(r[3]) : "r"(addr));
}

__device__ __forceinline__ void cpa16(uint32_t dst, const void* src) {
    asm volatile("cp.async.cg.shared.global [%0], [%1], 16;" :: "r"(dst), "l"(src));
}
__device__ __forceinline__ void cpa_commit() {
    asm volatile("cp.async.commit_group;" ::: "memory");
}
__device__ __forceinline__ uint32_t smem_u32(const void* p) {
    uint32_t a;
    asm("{ .reg .u64 t; cvta.to.shared.u64 t, %1; cvt.u32.u64 %0, t; }"
        : "=r"(a) : "l"(p));
    return a;
}

// ===========================================================================
// Pure-fp16 3-product GEMM (Markidis):  C[M,N] = op(A @ B^T + bias)
// A given as hi/lo half [M,K] row-major; B as hi/lo half [N,K] row-major.
// 128x128 block tile, BK=32, 3-stage cp.async pipeline, XOR-swizzled smem,
// ldmatrix fragment loads. 8 warps (2M x 4N), warp tile 64x32.
// M,N div 128; K div 32. OUT_HALF: write hi/lo half pair instead of fp32.
// ===========================================================================
#define ARR_HALFS   (128 * 32)             // 4096 halves = 8KB
#define STAGE_HALFS (4 * ARR_HALFS)        // Ah, Al, Bh, Bl
#define GSM_BYTES   (3 * STAGE_HALFS * 2)  // 96KB

template<int EPI_COS, int OUT_HALF>
__global__ __launch_bounds__(256, 2)
void gemmh(const __half* __restrict__ Ah, const __half* __restrict__ Al,
           const __half* __restrict__ Bh, const __half* __restrict__ Bl,
           const float* __restrict__ bias,
           float* __restrict__ C, __half* __restrict__ Ch, __half* __restrict__ Cl,
           int M, int N, int K, long sA, long sB, long sC)
{
    extern __shared__ __half sm[];
    const uint32_t smb = smem_u32(sm);

    Ah += (long)blockIdx.z * sA;  Al += (long)blockIdx.z * sA;
    Bh += (long)blockIdx.z * sB;  Bl += (long)blockIdx.z * sB;

    const int m0 = blockIdx.y * 128;
    const int n0 = blockIdx.x * 128;
    const int t    = threadIdx.x;
    const int lane = t & 31;
    const int w    = t >> 5;
    const int g    = lane >> 2;   // 0..7
    const int tg   = lane & 3;    // 0..3
    const int wm   = w & 1;
    const int wn   = w >> 1;

    const int KT = K / 32;

    // ---- producer: 8 cp.async of 16B per thread per stage ----
    auto stage_load = [&](int s, int kt) {
        const long kb = (long)kt * 32;
#pragma unroll
        for (int h = 0; h < 2; ++h) {
            const int c   = t + h * 256;          // 0..511
            const int row = c >> 2, q = c & 3;
            const int pq  = q ^ ((row >> 1) & 3);
            const uint32_t so = smb + (uint32_t)(s * STAGE_HALFS + row * 32 + pq * 8) * 2;
            const long ga = (long)(m0 + row) * K + kb + q * 8;
            const long gb = (long)(n0 + row) * K + kb + q * 8;
            cpa16(so,                     Ah + ga);
            cpa16(so + ARR_HALFS * 2,     Al + ga);
            cpa16(so + ARR_HALFS * 4,     Bh + gb);
            cpa16(so + ARR_HALFS * 6,     Bl + gb);
        }
        cpa_commit();
    };

    // ---- ldmatrix per-lane constants ----
    const int sub = lane >> 3, l8 = lane & 7;
    // A x4: matrices (m0-7,c0)(m8-15,c0)(m0-7,c1)(m8-15,c1)
    const int a_csel = sub >> 1;
    const int a_moff = (sub & 1) * 8 + l8;
    // B x4 over two n-tiles: (n0-7,c0)(n0-7,c1)(n8-15,c0)(n8-15,c1)
    const int b_csel = sub & 1;
    const int b_noff = (sub >> 1) * 8 + l8;

    uint32_t rA32[4], xqA[4];
#pragma unroll
    for (int mt = 0; mt < 4; ++mt) {
        const int row = wm * 64 + mt * 16 + a_moff;
        rA32[mt] = (uint32_t)row * 32;
        xqA[mt]  = (row >> 1) & 3;
    }
    uint32_t rB32[2], xqB[2];
#pragma unroll
    for (int np = 0; np < 2; ++np) {
        const int row = wn * 32 + np * 16 + b_noff;
        rB32[np] = (uint32_t)row * 32;
        xqB[np]  = (row >> 1) & 3;
    }

    float acc[4][4][4];
#pragma unroll
    for (int i = 0; i < 4; ++i)
#pragma unroll
        for (int j = 0; j < 4; ++j)
#pragma unroll
            for (int r = 0; r < 4; ++r) acc[i][j][r] = 0.f;

    stage_load(0, 0);
    stage_load(1, 1);

    for (int kt = 0; kt < KT; ++kt) {
        asm volatile("cp.async.wait_group 1;" ::: "memory");
        __syncthreads();
        if (kt + 2 < KT) stage_load((kt + 2) % 3, kt + 2);

        const uint32_t sAh = smb + (uint32_t)((kt % 3) * STAGE_HALFS) * 2;
        const uint32_t sAl = sAh + ARR_HALFS * 2;
        const uint32_t sBh = sAh + ARR_HALFS * 4;
        const uint32_t sBl = sAh + ARR_HALFS * 6;

#pragma unroll
        for (int ks = 0; ks < 2; ++ks) {
            const uint32_t qa = (uint32_t)(2 * ks + a_csel);
            const uint32_t qb = (uint32_t)(2 * ks + b_csel);

            uint32_t bh[4][2], bl[4][2];
#pragma unroll
            for (int np = 0; np < 2; ++np) {
                const uint32_t off = (rB32[np] + ((qb ^ xqB[np]) << 3)) * 2;
                uint32_t r[4];
                ldsm4(r, sBh + off);
                bh[np * 2][0] = r[0]; bh[np * 2][1] = r[1];
                bh[np * 2 + 1][0] = r[2]; bh[np * 2 + 1][1] = r[3];
                ldsm4(r, sBl + off);
                bl[np * 2][0] = r[0]; bl[np * 2][1] = r[1];
                bl[np * 2 + 1][0] = r[2]; bl[np * 2 + 1][1] = r[3];
            }
#pragma unroll
            for (int mt = 0; mt < 4; ++mt) {
                const uint32_t off = (rA32[mt] + ((qa ^ xqA[mt]) << 3)) * 2;
                uint32_t ah[4], al[4];
                ldsm4(ah, sAh + off);
                ldsm4(al, sAl + off);
#pragma unroll
                for (int nt = 0; nt < 4; ++nt) {
                    mma16(acc[mt][nt], ah, bh[nt]);
                    mma16(acc[mt][nt], al, bh[nt]);
                    mma16(acc[mt][nt], ah, bl[nt]);
                }
            }
        }
    }

    // epilogue: c0:(g,2tg) c1:(g,2tg+1) c2:(g+8,2tg) c3:(g+8,2tg+1)
#pragma unroll
    for (int mt = 0; mt < 4; ++mt) {
#pragma unroll
        for (int nt = 0; nt < 4; ++nt) {
            const int r0 = m0 + wm * 64 + mt * 16 + g;
            const int c0 = n0 + wn * 32 + nt * 8 + 2 * tg;
            float bv0 = 0.f, bv1 = 0.f;
            if (bias) { bv0 = bias[c0]; bv1 = bias[c0 + 1]; }
            float v00 = acc[mt][nt][0] + bv0;
            float v01 = acc[mt][nt][1] + bv1;
            float v10 = acc[mt][nt][2] + bv0;
            float v11 = acc[mt][nt][3] + bv1;
            if (EPI_COS) {
                v00 = cosf(v00); v01 = cosf(v01);
                v10 = cosf(v10); v11 = cosf(v11);
            }
            if (OUT_HALF) {
                __half2 h0 = __floats2half2_rn(v00, v01);
                __half2 h1 = __floats2half2_rn(v10, v11);
                __half2 l0 = __floats2half2_rn(v00 - __low2float(h0), v01 - __high2float(h0));
                __half2 l1 = __floats2half2_rn(v10 - __low2float(h1), v11 - __high2float(h1));
                long o0 = (long)blockIdx.z * sC + (long)r0 * N + c0;
                long o1 = o0 + 8L * N;
                *(uint32_t*)(Ch + o0) = h2u(h0);
                *(uint32_t*)(Cl + o0) = h2u(l0);
                *(uint32_t*)(Ch + o1) = h2u(h1);
                *(uint32_t*)(Cl + o1) = h2u(l1);
            } else {
                long o0 = (long)blockIdx.z * sC + (long)r0 * N + c0;
                *(float2*)(C + o0)          = make_float2(v00, v01);
                *(float2*)(C + o0 + 8L * N) = make_float2(v10, v11);
            }
        }
    }
}

// ===========================================================================
// Elementwise fp32 -> (hi,lo) fp16 convert. n divisible by 1024.
// ===========================================================================
__global__ void conv_hl(const float* __restrict__ src,
                        __half* __restrict__ h, __half* __restrict__ l)
{
    const long i = ((long)blockIdx.x * 256 + threadIdx.x) * 4;
    float4 v = *(const float4*)(src + i);
    __half2 h0 = __floats2half2_rn(v.x, v.y);
    __half2 h1 = __floats2half2_rn(v.z, v.w);
    __half2 l0 = __floats2half2_rn(v.x - __low2float(h0), v.y - __high2float(h0));
    __half2 l1 = __floats2half2_rn(v.z - __low2float(h1), v.w - __high2float(h1));
    *(uint2*)(h + i) = make_uint2(h2u(h0), h2u(h1));
    *(uint2*)(l + i) = make_uint2(h2u(l0), h2u(l1));
}

// ===========================================================================
// Transpose + convert: dst_{h,l}[z][c][r] = split(src[z][r][c]); R,C div 32
// ===========================================================================
__global__ void convT_hl(const float* __restrict__ src,
                         __half* __restrict__ dh, __half* __restrict__ dl,
                         int R, int C)
{
    __shared__ float tile[32][33];
    const long zo = (long)blockIdx.z * R * C;
    const int c0 = blockIdx.x * 32, r0 = blockIdx.y * 32;
    const int x = threadIdx.x, y = threadIdx.y;   // 32 x 8
#pragma unroll
    for (int j = 0; j < 32; j += 8)
        tile[y + j][x] = src[zo + (long)(r0 + y + j) * C + c0 + x];
    __syncthreads();
#pragma unroll
    for (int j = 0; j < 32; j += 8) {
        float v = tile[x][y + j];
        __half hh = __float2half_rn(v);
        long o = zo + (long)(c0 + y + j) * R + r0 + x;
        dh[o] = hh;
        dl[o] = __float2half_rn(v - __half2float(hh));
    }
}

// ---------------------------------------------------------------------------
// bkr[r] = br[r] + sum_d bk[d] * Wr[d, r]
__global__ void bkr_kernel(const float* __restrict__ bk,
                           const float* __restrict__ Wr,
                           const float* __restrict__ br,
                           float* __restrict__ bkr, int D)
{
    const int r = blockIdx.x;
    const int t = threadIdx.x;
    float s = 0.f;
    for (int d = t; d < D; d += 128)
        s += bk[d] * Wr[(long)d * D + r];
#pragma unroll
    for (int o = 16; o > 0; o >>= 1) s += __shfl_xor_sync(0xffffffffu, s, o);
    __shared__ float red[4];
    if ((t & 31) == 0) red[t >> 5] = s;
    __syncthreads();
    if (t == 0) bkr[r] = red[0] + red[1] + red[2] + red[3] + br[r];
}

// ---------------------------------------------------------------------------
// Row softmax over 2048 cols; writes probs as hi/lo half pair.
__global__ void softmax_rows(const float* __restrict__ scores,
                             __half* __restrict__ ph, __half* __restrict__ pl)
{
    const int NCOL = S_;
    const float* p = scores + (long)blockIdx.x * NCOL;
    const int t = threadIdx.x;

    __shared__ float red[32];

    float v[NCOL / 256];
#pragma unroll
    for (int i = 0; i < NCOL / 256; ++i) v[i] = p[t + i * 256];

    float mx = v[0];
#pragma unroll
    for (int i = 1; i < NCOL / 256; ++i) mx = fmaxf(mx, v[i]);
#pragma unroll
    for (int o = 16; o > 0; o >>= 1) mx = fmaxf(mx, __shfl_xor_sync(0xffffffffu, mx, o));
    if ((t & 31) == 0) red[t >> 5] = mx;
    __syncthreads();
    if (t == 0) {
        float m = red[0];
        for (int i = 1; i < 8; ++i) m = fmaxf(m, red[i]);
        red[0] = m;
    }
    __syncthreads();
    mx = red[0];

    float s = 0.f;
#pragma unroll
    for (int i = 0; i < NCOL / 256; ++i) { v[i] = expf(v[i] - mx); s += v[i]; }
#pragma unroll
    for (int o = 16; o > 0; o >>= 1) s += __shfl_xor_sync(0xffffffffu, s, o);
    __syncthreads();
    if ((t & 31) == 0) red[t >> 5] = s;
    __syncthreads();
    if (t == 0) {
        float ss = 0.f;
        for (int i = 0; i < 8; ++i) ss += red[i];
        red[0] = 1.f / ss;
    }
    __syncthreads();
    const float inv = red[0];

    __half* hp = ph + (long)blockIdx.x * NCOL;
    __half* lp = pl + (long)blockIdx.x * NCOL;
#pragma unroll
    for (int i = 0; i < NCOL / 256; ++i) {
        float pv = v[i] * inv;
        __half hh = __float2half_rn(pv);
        hp[t + i * 256] = hh;
        lp[t + i * 256] = __float2half_rn(pv - __half2float(hh));
    }
}

// ---------------------------------------------------------------------------
extern "C" void kernel_launch(void* const* d_in, const int* in_sizes, int n_in,
                              void* d_out, int out_size)
{
    const float* x  = (const float*)d_in[0];
    const float* y  = (const float*)d_in[1];
    const float* Wq = (const float*)d_in[2];
    const float* bq = (const float*)d_in[3];
    const float* Wk = (const float*)d_in[4];
    const float* bk = (const float*)d_in[5];
    const float* Wv = (const float*)d_in[6];
    const float* bv = (const float*)d_in[7];
    const float* Wr = (const float*)d_in[8];
    const float* br = (const float*)d_in[9];
    float* out = (float*)d_out;

    __half *Xh, *Xl, *Yh, *Yl, *Qh, *Ql, *Khh, *Khl, *VTh, *VTl, *Ph, *Pl;
    __half *WrTh, *WrTl, *WqTh, *WqTl, *WvTh, *WvTl, *Wkh, *Wkl, *WkrTh, *WkrTl;
    float *V, *Sc, *bkr;
    cudaGetSymbolAddress((void**)&Xh, g_Xh);   cudaGetSymbolAddress((void**)&Xl, g_Xl);
    cudaGetSymbolAddress((void**)&Yh, g_Yh);   cudaGetSymbolAddress((void**)&Yl, g_Yl);
    cudaGetSymbolAddress((void**)&Qh, g_Qh);   cudaGetSymbolAddress((void**)&Ql, g_Ql);
    cudaGetSymbolAddress((void**)&Khh, g_Khh); cudaGetSymbolAddress((void**)&Khl, g_Khl);
    cudaGetSymbolAddress((void**)&VTh, g_VTh); cudaGetSymbolAddress((void**)&VTl, g_VTl);
    cudaGetSymbolAddress((void**)&Ph, g_Ph);   cudaGetSymbolAddress((void**)&Pl, g_Pl);
    cudaGetSymbolAddress((void**)&WrTh, g_WrTh); cudaGetSymbolAddress((void**)&WrTl, g_WrTl);
    cudaGetSymbolAddress((void**)&WqTh, g_WqTh); cudaGetSymbolAddress((void**)&WqTl, g_WqTl);
    cudaGetSymbolAddress((void**)&WvTh, g_WvTh); cudaGetSymbolAddress((void**)&WvTl, g_WvTl);
    cudaGetSymbolAddress((void**)&Wkh, g_Wkh);   cudaGetSymbolAddress((void**)&Wkl, g_Wkl);
    cudaGetSymbolAddress((void**)&WkrTh, g_WkrTh); cudaGetSymbolAddress((void**)&WkrTl, g_WkrTl);
    cudaGetSymbolAddress((void**)&V, g_V);
    cudaGetSymbolAddress((void**)&Sc, g_S);
    cudaGetSymbolAddress((void**)&bkr, g_bkr);

    cudaFuncSetAttribute(gemmh<0,0>, cudaFuncAttributeMaxDynamicSharedMemorySize, GSM_BYTES);
    cudaFuncSetAttribute(gemmh<0,1>, cudaFuncAttributeMaxDynamicSharedMemorySize, GSM_BYTES);
    cudaFuncSetAttribute(gemmh<1,1>, cudaFuncAttributeMaxDynamicSharedMemorySize, GSM_BYTES);

    dim3 tb(32, 8);

    // 0) bkr = bk @ Wr + br
    bkr_kernel<<<D_, 128>>>(bk, Wr, br, bkr, D_);

    // 1) convert inputs / weights
    conv_hl<<<BS_ * D_ / 1024, 256>>>(x, Xh, Xl);
    conv_hl<<<BS_ * D_ / 1024, 256>>>(y, Yh, Yl);
    conv_hl<<<D_ * D_ / 1024, 256>>>(Wk, Wkh, Wkl);
    {
        dim3 g(D_ / 32, D_ / 32, 1);
        convT_hl<<<g, tb>>>(Wr, WrTh, WrTl, D_, D_);
        convT_hl<<<g, tb>>>(Wq, WqTh, WqTl, D_, D_);
        convT_hl<<<g, tb>>>(Wv, WvTh, WvTl, D_, D_);
    }

    // 2) WkrT = Wr^T @ Wk^T  (A = WrT [r,e], B = Wk [d,e]) -> half pair
    {
        dim3 g(D_ / 128, D_ / 128, 1);
        gemmh<0,1><<<g, 256, GSM_BYTES>>>(WrTh, WrTl, Wkh, Wkl, nullptr,
                                          nullptr, WkrTh, WkrTl, D_, D_, D_, 0, 0, 0);
    }

    // 3) Q = x @ Wq + bq -> half pair
    {
        dim3 g(D_ / 128, BS_ / 128, 1);
        gemmh<0,1><<<g, 256, GSM_BYTES>>>(Xh, Xl, WqTh, WqTl, bq,
                                          nullptr, Qh, Ql, BS_, D_, D_, 0, 0, 0);
    }

    // 4) Kh = cos(y @ Wkr + bkr) -> half pair
    {
        dim3 g(D_ / 128, BS_ / 128, 1);
        gemmh<1,1><<<g, 256, GSM_BYTES>>>(Yh, Yl, WkrTh, WkrTl, bkr,
                                          nullptr, Khh, Khl, BS_, D_, D_, 0, 0, 0);
    }

    // 5) V = y @ Wv + bv -> fp32
    {
        dim3 g(D_ / 128, BS_ / 128, 1);
        gemmh<0,0><<<g, 256, GSM_BYTES>>>(Yh, Yl, WvTh, WvTl, bv,
                                          V, nullptr, nullptr, BS_, D_, D_, 0, 0, 0);
    }

    // 6) VT[b] = split(V[b]^T)  ([S,D] -> [D,S] per batch)
    {
        dim3 g(D_ / 32, S_ / 32, B_);
        convT_hl<<<g, tb>>>(V, VTh, VTl, S_, D_);
    }

    // 7) scores[b] = Q[b] @ Kh[b]^T -> fp32
    {
        dim3 g(S_ / 128, S_ / 128, B_);
        gemmh<0,0><<<g, 256, GSM_BYTES>>>(Qh, Ql, Khh, Khl, nullptr,
                                          Sc, nullptr, nullptr, S_, S_, D_,
                                          (long)S_ * D_, (long)S_ * D_, (long)S_ * S_);
    }

    // 8) softmax rows -> probs half pair
    softmax_rows<<<B_ * S_, 256>>>(Sc, Ph, Pl);

    // 9) out[b] = P[b] @ VT[b]^T -> fp32
    {
        dim3 g(D_ / 128, S_ / 128, B_);
        gemmh<0,0><<<g, 256, GSM_BYTES>>>(Ph, Pl, VTh, VTl, nullptr,
                                          out, nullptr, nullptr, S_, D_, S_,
                                          (long)S_ * S_, (long)D_ * S_, (long)S_ * D_);
    }
}